// round 3
// baseline (speedup 1.0000x reference)
#include <cuda_runtime.h>
#include <cuda_bf16.h>
#include <cstdint>

#define DI __device__ __forceinline__

#define HID   256
#define KP1   320        // word dim 300 padded to 320
#define KP2   512
#define MLEAF 262144
#define VOCAB 50257
#define TPB   256

// ---- shared memory layout (dynamic) ----
#define SM_IDS 0                    // 128 ints
#define SM_AHI 1024                 // 128 rows x 128B
#define SM_ALO (SM_AHI + 16384)
#define SM_BHI (SM_ALO + 16384)
#define SM_BLO (SM_BHI + 16384)
#define SMEM_SZ (SM_BLO + 16384)    // 66560 B -> 2 CTAs/SM

// ---- static device scratch (no allocation allowed) ----
__device__ __nv_bfloat16 g_w1h[HID * KP1];
__device__ __nv_bfloat16 g_w1l[HID * KP1];
__device__ __nv_bfloat16 g_w2h[HID * KP2];
__device__ __nv_bfloat16 g_w2l[HID * KP2];
__device__ __nv_bfloat16 g_eh[(size_t)VOCAB * KP1];       // 32 MB
__device__ __nv_bfloat16 g_el[(size_t)VOCAB * KP1];
__device__ __nv_bfloat16 g_p0h[(size_t)MLEAF * HID];      // 134 MB
__device__ __nv_bfloat16 g_p0l[(size_t)MLEAF * HID];
__device__ __nv_bfloat16 g_p1h[(size_t)(MLEAF / 2) * HID];
__device__ __nv_bfloat16 g_p1l[(size_t)(MLEAF / 2) * HID];

// ---------------- PTX helpers (compute_103-safe ISA only) ----------------
DI uint32_t smem_u32(const void* p) {
    uint32_t a;
    asm("{ .reg .u64 t; cvta.to.shared.u64 t, %1; cvt.u32.u64 %0, t; }" : "=r"(a) : "l"(p));
    return a;
}

#define CPA16(dst, src) \
    asm volatile("cp.async.cg.shared.global [%0], [%1], 16;" :: "r"(dst), "l"(src))
#define CPA_COMMIT_WAIT() \
    asm volatile("cp.async.commit_group;\n\tcp.async.wait_group 0;" ::: "memory")

#define LDSM4(r0, r1, r2, r3, addr)                                            \
    asm volatile("ldmatrix.sync.aligned.m8n8.x4.shared.b16 {%0,%1,%2,%3}, [%4];" \
                 : "=r"(r0), "=r"(r1), "=r"(r2), "=r"(r3) : "r"(addr))

#define MMA16816(d, a, b0, b1)                                                 \
    asm volatile("mma.sync.aligned.m16n8k16.row.col.f32.bf16.bf16.f32 "        \
                 "{%0,%1,%2,%3}, {%4,%5,%6,%7}, {%8,%9}, {%0,%1,%2,%3};"       \
                 : "+f"((d)[0]), "+f"((d)[1]), "+f"((d)[2]), "+f"((d)[3])      \
                 : "r"((a)[0]), "r"((a)[1]), "r"((a)[2]), "r"((a)[3]),         \
                   "r"(b0), "r"(b1))

DI void split2(float v, __nv_bfloat16& h, __nv_bfloat16& l) {
    h = __float2bfloat16(v);
    l = __float2bfloat16(v - __bfloat162float(h));
}

// ---------------- prep: split weights (transposed+padded) ----------------
__global__ void prep_w(const float* __restrict__ W1, const float* __restrict__ W2) {
    int i = blockIdx.x * blockDim.x + threadIdx.x;
    if (i < HID * KP1) {
        int n = i / KP1, k = i % KP1;
        float v = (k < 300) ? W1[k * HID + n] : 0.0f;
        __nv_bfloat16 h, l;
        split2(v, h, l);
        g_w1h[i] = h; g_w1l[i] = l;
    } else {
        int j = i - HID * KP1;
        if (j < HID * KP2) {
            int n = j / KP2, k = j % KP2;
            __nv_bfloat16 h, l;
            split2(W2[k * HID + n], h, l);
            g_w2h[j] = h; g_w2l[j] = l;
        }
    }
}

// ---------------- prep: split embedding table (padded to 320) ----------------
__global__ void prep_emb(const float* __restrict__ E) {
    size_t i = (size_t)blockIdx.x * blockDim.x + threadIdx.x;
    if (i >= (size_t)VOCAB * KP1) return;
    int v = (int)(i / KP1), k = (int)(i % KP1);
    float x = (k < 300) ? E[(size_t)v * 300 + k] : 0.0f;
    __nv_bfloat16 h, l;
    split2(x, h, l);
    g_eh[i] = h; g_el[i] = l;
}

// ---------------- GEMM: Out[128,128-slice] = A[128,KPAD] @ Wt[128,KPAD]^T + bias ----
// LEAF: A row r comes from emb planes at ids[m0+r]. Split-bf16 3-MMA (hh+hl+lh).
template <int LEAF, int KPAD, int FINAL>
__global__ void __launch_bounds__(TPB, 2) gemm_kernel(
    const int* __restrict__ ids,
    const __nv_bfloat16* __restrict__ Ah, const __nv_bfloat16* __restrict__ Al,
    const __nv_bfloat16* __restrict__ Bh, const __nv_bfloat16* __restrict__ Bl,
    const float* __restrict__ bias,
    __nv_bfloat16* __restrict__ Oh, __nv_bfloat16* __restrict__ Ol,
    float* __restrict__ Of)
{
    extern __shared__ char smem[];
    const int tid = threadIdx.x, wid = tid >> 5, lid = tid & 31;
    const int m0 = blockIdx.x * 128, n0 = blockIdx.y * 128;
    const int wm = wid >> 2, wn = wid & 3;              // 2 x 4 warp grid

    if (LEAF && tid < 128) ((int*)smem)[tid] = ids[m0 + tid];
    __syncthreads();

    const uint32_t s_ahi = smem_u32(smem + SM_AHI);
    const uint32_t s_alo = smem_u32(smem + SM_ALO);
    const uint32_t s_bhi = smem_u32(smem + SM_BHI);
    const uint32_t s_blo = smem_u32(smem + SM_BLO);

    float acc[4][4][4];
    #pragma unroll
    for (int i = 0; i < 4; i++)
        #pragma unroll
        for (int j = 0; j < 4; j++)
            #pragma unroll
            for (int c = 0; c < 4; c++) acc[i][j][c] = 0.0f;

    const int NCH = KPAD / 64;
    for (int ch = 0; ch < NCH; ch++) {
        const int k0 = ch * 64;
        // ---- load tiles: 4 planes x 128 rows x 8 x 16B via cp.async ----
        #pragma unroll
        for (int v = tid; v < 1024; v += TPB) {          // A hi
            int r = v >> 3, u = v & 7;
            const char* src;
            if (LEAF) {
                int id = ((const int*)smem)[r];
                src = (const char*)(Ah + (size_t)id * KPAD + k0) + u * 16;
            } else {
                src = (const char*)(Ah + (size_t)(m0 + r) * KPAD + k0) + u * 16;
            }
            CPA16(s_ahi + r * 128 + ((u ^ (r & 7)) << 4), src);
        }
        #pragma unroll
        for (int v = tid; v < 1024; v += TPB) {          // A lo
            int r = v >> 3, u = v & 7;
            const char* src;
            if (LEAF) {
                int id = ((const int*)smem)[r];
                src = (const char*)(Al + (size_t)id * KPAD + k0) + u * 16;
            } else {
                src = (const char*)(Al + (size_t)(m0 + r) * KPAD + k0) + u * 16;
            }
            CPA16(s_alo + r * 128 + ((u ^ (r & 7)) << 4), src);
        }
        #pragma unroll
        for (int v = tid; v < 1024; v += TPB) {          // B hi
            int r = v >> 3, u = v & 7;
            const char* src = (const char*)(Bh + (size_t)(n0 + r) * KPAD + k0) + u * 16;
            CPA16(s_bhi + r * 128 + ((u ^ (r & 7)) << 4), src);
        }
        #pragma unroll
        for (int v = tid; v < 1024; v += TPB) {          // B lo
            int r = v >> 3, u = v & 7;
            const char* src = (const char*)(Bl + (size_t)(n0 + r) * KPAD + k0) + u * 16;
            CPA16(s_blo + r * 128 + ((u ^ (r & 7)) << 4), src);
        }
        CPA_COMMIT_WAIT();
        __syncthreads();

        // ---- compute: 4 k16 steps, 3 split passes each ----
        #pragma unroll
        for (int ks = 0; ks < 4; ks++) {
            uint32_t a[4][4], bh[4][2], bl[4][2];

            // A addresses: tile i -> rows wm*64+i*16+(lid&15), col16 = ks*2+(lid>>4)
            #pragma unroll
            for (int i = 0; i < 4; i++) {
                int row = wm * 64 + i * 16 + (lid & 15);
                int col = ks * 2 + (lid >> 4);
                LDSM4(a[i][0], a[i][1], a[i][2], a[i][3],
                      s_ahi + row * 128 + ((col ^ (row & 7)) << 4));
            }
            // B hi: 2x ldmatrix.x4, each covers 2 n8-frags
            #pragma unroll
            for (int p = 0; p < 2; p++) {
                int row = wn * 32 + p * 16 + ((lid & 7) + ((lid >> 4) << 3));
                int col = ks * 2 + ((lid >> 3) & 1);
                LDSM4(bh[2 * p][0], bh[2 * p][1], bh[2 * p + 1][0], bh[2 * p + 1][1],
                      s_bhi + row * 128 + ((col ^ (row & 7)) << 4));
            }
            // pass 1: A_hi x B_hi
            #pragma unroll
            for (int i = 0; i < 4; i++)
                #pragma unroll
                for (int j = 0; j < 4; j++)
                    MMA16816(acc[i][j], a[i], bh[j][0], bh[j][1]);

            // B lo
            #pragma unroll
            for (int p = 0; p < 2; p++) {
                int row = wn * 32 + p * 16 + ((lid & 7) + ((lid >> 4) << 3));
                int col = ks * 2 + ((lid >> 3) & 1);
                LDSM4(bl[2 * p][0], bl[2 * p][1], bl[2 * p + 1][0], bl[2 * p + 1][1],
                      s_blo + row * 128 + ((col ^ (row & 7)) << 4));
            }
            // pass 2: A_hi x B_lo
            #pragma unroll
            for (int i = 0; i < 4; i++)
                #pragma unroll
                for (int j = 0; j < 4; j++)
                    MMA16816(acc[i][j], a[i], bl[j][0], bl[j][1]);

            // A lo (overwrite a)
            #pragma unroll
            for (int i = 0; i < 4; i++) {
                int row = wm * 64 + i * 16 + (lid & 15);
                int col = ks * 2 + (lid >> 4);
                LDSM4(a[i][0], a[i][1], a[i][2], a[i][3],
                      s_alo + row * 128 + ((col ^ (row & 7)) << 4));
            }
            // pass 3: A_lo x B_hi
            #pragma unroll
            for (int i = 0; i < 4; i++)
                #pragma unroll
                for (int j = 0; j < 4; j++)
                    MMA16816(acc[i][j], a[i], bh[j][0], bh[j][1]);
        }
        __syncthreads();   // protect smem before next chunk's cp.async
    }

    // ---- epilogue: +bias, write fp32 (final) or split bf16 planes ----
    #pragma unroll
    for (int i = 0; i < 4; i++) {
        int r0 = m0 + wm * 64 + i * 16 + (lid >> 2);
        #pragma unroll
        for (int j = 0; j < 4; j++) {
            int gc = n0 + wn * 32 + j * 8 + 2 * (lid & 3);
            float b0 = bias[gc], b1 = bias[gc + 1];
            float v00 = acc[i][j][0] + b0, v01 = acc[i][j][1] + b1;
            float v10 = acc[i][j][2] + b0, v11 = acc[i][j][3] + b1;
            if (FINAL) {
                *(float2*)(Of + (size_t)r0 * HID + gc)        = make_float2(v00, v01);
                *(float2*)(Of + (size_t)(r0 + 8) * HID + gc)  = make_float2(v10, v11);
            } else {
                __nv_bfloat16 h0, l0, h1, l1;
                split2(v00, h0, l0); split2(v01, h1, l1);
                union { __nv_bfloat16 b[2]; uint32_t u; } ph, pl;
                ph.b[0] = h0; ph.b[1] = h1; pl.b[0] = l0; pl.b[1] = l1;
                *(uint32_t*)(Oh + (size_t)r0 * HID + gc) = ph.u;
                *(uint32_t*)(Ol + (size_t)r0 * HID + gc) = pl.u;
                split2(v10, h0, l0); split2(v11, h1, l1);
                ph.b[0] = h0; ph.b[1] = h1; pl.b[0] = l0; pl.b[1] = l1;
                *(uint32_t*)(Oh + (size_t)(r0 + 8) * HID + gc) = ph.u;
                *(uint32_t*)(Ol + (size_t)(r0 + 8) * HID + gc) = pl.u;
            }
        }
    }
}

// ---------------- driver ----------------
extern "C" void kernel_launch(void* const* d_in, const int* in_sizes, int n_in,
                              void* d_out, int out_size) {
    const int*   ids = (const int*)d_in[0];
    const float* emb = (const float*)d_in[1];
    const float* W1  = (const float*)d_in[2];
    const float* b1  = (const float*)d_in[3];
    const float* W2  = (const float*)d_in[4];
    const float* b2  = (const float*)d_in[5];
    float* out = (float*)d_out;

    __nv_bfloat16 *w1h, *w1l, *w2h, *w2l, *eh, *el, *p0h, *p0l, *p1h, *p1l;
    cudaGetSymbolAddress((void**)&w1h, g_w1h);
    cudaGetSymbolAddress((void**)&w1l, g_w1l);
    cudaGetSymbolAddress((void**)&w2h, g_w2h);
    cudaGetSymbolAddress((void**)&w2l, g_w2l);
    cudaGetSymbolAddress((void**)&eh, g_eh);
    cudaGetSymbolAddress((void**)&el, g_el);
    cudaGetSymbolAddress((void**)&p0h, g_p0h);
    cudaGetSymbolAddress((void**)&p0l, g_p0l);
    cudaGetSymbolAddress((void**)&p1h, g_p1h);
    cudaGetSymbolAddress((void**)&p1l, g_p1l);

    cudaFuncSetAttribute(gemm_kernel<1, KP1, 0>, cudaFuncAttributeMaxDynamicSharedMemorySize, SMEM_SZ);
    cudaFuncSetAttribute(gemm_kernel<0, KP2, 0>, cudaFuncAttributeMaxDynamicSharedMemorySize, SMEM_SZ);
    cudaFuncSetAttribute(gemm_kernel<0, KP2, 1>, cudaFuncAttributeMaxDynamicSharedMemorySize, SMEM_SZ);

    prep_w<<<(HID * KP1 + HID * KP2 + 255) / 256, 256>>>(W1, W2);
    prep_emb<<<(int)(((size_t)VOCAB * KP1 + 255) / 256), 256>>>(emb);

    // leaves: [262144, 320] @ W1t -> p0 planes [262144, 256]
    {
        dim3 g(MLEAF / 128, 2);
        gemm_kernel<1, KP1, 0><<<g, TPB, SMEM_SZ>>>(
            ids, eh, el, w1h, w1l, b1, p0h, p0l, nullptr);
    }

    // internal levels: view [rows,256] planes as [rows/2,512]
    int rows = MLEAF;
    __nv_bfloat16 *ch = p0h, *cl = p0l, *oh = p1h, *ol = p1l;
    while (rows > 256) {
        int mout = rows / 2;
        dim3 g(mout / 128, 2);
        if (mout == 256) {
            gemm_kernel<0, KP2, 1><<<g, TPB, SMEM_SZ>>>(
                nullptr, ch, cl, w2h, w2l, b2, nullptr, nullptr, out);
        } else {
            gemm_kernel<0, KP2, 0><<<g, TPB, SMEM_SZ>>>(
                nullptr, ch, cl, w2h, w2l, b2, oh, ol, nullptr);
        }
        __nv_bfloat16* th = ch; __nv_bfloat16* tl = cl;
        ch = oh; cl = ol; oh = th; ol = tl;
        rows = mout;
    }
}

// round 9
// speedup vs baseline: 1.0280x; 1.0280x over previous
#include <cuda_runtime.h>
#include <cuda_bf16.h>
#include <cstdint>

#define DI __device__ __forceinline__

#define HID   256
#define KP1   320        // word dim 300 padded to 320
#define KP2   512
#define MLEAF 262144
#define VOCAB 50257
#define TPB   256

// ---- shared memory layout: 2-stage pipeline, K-chunk 32 (64B rows) ----
// stage s at 1024 + s*32768; planes AHI/ALO/BHI/BLO each 128 rows x 64B = 8KB
#define SM_IDS   0
#define SM_STAGE 1024
#define STG_SZ   32768
#define PL_SZ    8192
#define SMEM_SZ  (SM_STAGE + 2 * STG_SZ)   // 66560 B -> 2 CTAs/SM

// ---- static device scratch (no allocation allowed) ----
__device__ __align__(256) __nv_bfloat16 g_w1h[HID * KP1];
__device__ __align__(256) __nv_bfloat16 g_w1l[HID * KP1];
__device__ __align__(256) __nv_bfloat16 g_w2h[HID * KP2];
__device__ __align__(256) __nv_bfloat16 g_w2l[HID * KP2];
__device__ __align__(256) __nv_bfloat16 g_eh[(size_t)VOCAB * KP1];
__device__ __align__(256) __nv_bfloat16 g_el[(size_t)VOCAB * KP1];
__device__ __align__(256) __nv_bfloat16 g_p0h[(size_t)MLEAF * HID];
__device__ __align__(256) __nv_bfloat16 g_p0l[(size_t)MLEAF * HID];
__device__ __align__(256) __nv_bfloat16 g_p1h[(size_t)(MLEAF / 2) * HID];
__device__ __align__(256) __nv_bfloat16 g_p1l[(size_t)(MLEAF / 2) * HID];

// ---------------- PTX helpers (compute_103-safe ISA only) ----------------
DI uint32_t smem_u32(const void* p) {
    uint32_t a;
    asm("{ .reg .u64 t; cvta.to.shared.u64 t, %1; cvt.u32.u64 %0, t; }" : "=r"(a) : "l"(p));
    return a;
}

#define CPA16(dst, src) \
    asm volatile("cp.async.cg.shared.global [%0], [%1], 16;" :: "r"(dst), "l"(src))
#define CPA_COMMIT() \
    asm volatile("cp.async.commit_group;" ::: "memory")
#define CPA_WAIT(n) \
    asm volatile("cp.async.wait_group %0;" :: "n"(n) : "memory")

#define LDSM4(r0, r1, r2, r3, addr)                                            \
    asm volatile("ldmatrix.sync.aligned.m8n8.x4.shared.b16 {%0,%1,%2,%3}, [%4];" \
                 : "=r"(r0), "=r"(r1), "=r"(r2), "=r"(r3) : "r"(addr))

#define MMA16816(d, a, b0, b1)                                                 \
    asm volatile("mma.sync.aligned.m16n8k16.row.col.f32.bf16.bf16.f32 "        \
                 "{%0,%1,%2,%3}, {%4,%5,%6,%7}, {%8,%9}, {%0,%1,%2,%3};"       \
                 : "+f"((d)[0]), "+f"((d)[1]), "+f"((d)[2]), "+f"((d)[3])      \
                 : "r"((a)[0]), "r"((a)[1]), "r"((a)[2]), "r"((a)[3]),         \
                   "r"(b0), "r"(b1))

DI void split2(float v, __nv_bfloat16& h, __nv_bfloat16& l) {
    h = __float2bfloat16(v);
    l = __float2bfloat16(v - __bfloat162float(h));
}

// 64B-row swizzle: XOR col16 bits[4:5] with row bits (byte bits[7:8])
DI uint32_t sw64(uint32_t off) { return off ^ ((off >> 3) & 0x30); }

// ---------------- prep: split weights (transposed+padded) ----------------
__global__ void prep_w(const float* __restrict__ W1, const float* __restrict__ W2) {
    int i = blockIdx.x * blockDim.x + threadIdx.x;
    if (i < HID * KP1) {
        int n = i / KP1, k = i % KP1;
        float v = (k < 300) ? W1[k * HID + n] : 0.0f;
        __nv_bfloat16 h, l;
        split2(v, h, l);
        g_w1h[i] = h; g_w1l[i] = l;
    } else {
        int j = i - HID * KP1;
        if (j < HID * KP2) {
            int n = j / KP2, k = j % KP2;
            __nv_bfloat16 h, l;
            split2(W2[k * HID + n], h, l);
            g_w2h[j] = h; g_w2l[j] = l;
        }
    }
}

// ---------------- prep: split embedding table (padded to 320) ----------------
__global__ void prep_emb(const float* __restrict__ E) {
    size_t i = (size_t)blockIdx.x * blockDim.x + threadIdx.x;
    if (i >= (size_t)VOCAB * KP1) return;
    int v = (int)(i / KP1), k = (int)(i % KP1);
    float x = (k < 300) ? E[(size_t)v * 300 + k] : 0.0f;
    __nv_bfloat16 h, l;
    split2(x, h, l);
    g_eh[i] = h; g_el[i] = l;
}

// ---------------- GEMM: Out[128,128] = A[128,KPAD] @ Wt[128,KPAD]^T + bias ----
// Split-bf16 3-MMA (hh + hl + lh), 2-stage cp.async pipeline over K-chunks of 32.
template <int LEAF, int KPAD, int FINAL>
__global__ void __launch_bounds__(TPB, 2) gemm_kernel(
    const int* __restrict__ ids,
    const __nv_bfloat16* __restrict__ Ah, const __nv_bfloat16* __restrict__ Al,
    const __nv_bfloat16* __restrict__ Bh, const __nv_bfloat16* __restrict__ Bl,
    const float* __restrict__ bias,
    __nv_bfloat16* __restrict__ Oh, __nv_bfloat16* __restrict__ Ol,
    float* __restrict__ Of)
{
    extern __shared__ char smem[];
    const int tid = threadIdx.x, wid = tid >> 5, lid = tid & 31;
    const int m0 = blockIdx.x * 128, n0 = blockIdx.y * 128;
    const int wm = wid >> 2, wn = wid & 3;              // 2 x 4 warp grid

    if (LEAF && tid < 128) ((int*)smem)[tid] = ids[m0 + tid];
    __syncthreads();

    const uint32_t s_base = smem_u32(smem + SM_STAGE);
    const int NCH = KPAD / 32;

    // loader: issue all cp.async for chunk ch into stage st (2048 x 16B)
    auto load_chunk = [&](int ch, int st) {
        const uint32_t stg = s_base + (uint32_t)st * STG_SZ;
        const int k0b = ch * 64;                         // chunk byte offset in K
        #pragma unroll
        for (int v = tid; v < 512; v += TPB) {           // A hi + A lo
            int r = v >> 2, u = v & 3;
            size_t rowoff;
            if (LEAF) {
                int id = ((const int*)smem)[r];
                rowoff = (size_t)id * KPAD;
            } else {
                rowoff = (size_t)(m0 + r) * KPAD;
            }
            uint32_t d = sw64((uint32_t)(r * 64 + u * 16));
            CPA16(stg + d,           (const char*)(Ah + rowoff) + k0b + u * 16);
            CPA16(stg + PL_SZ + d,   (const char*)(Al + rowoff) + k0b + u * 16);
        }
        #pragma unroll
        for (int v = tid; v < 512; v += TPB) {           // B hi + B lo
            int r = v >> 2, u = v & 3;
            size_t rowoff = (size_t)(n0 + r) * KPAD;
            uint32_t d = sw64((uint32_t)(r * 64 + u * 16));
            CPA16(stg + 2 * PL_SZ + d, (const char*)(Bh + rowoff) + k0b + u * 16);
            CPA16(stg + 3 * PL_SZ + d, (const char*)(Bl + rowoff) + k0b + u * 16);
        }
        CPA_COMMIT();
    };

    float acc[4][4][4];
    #pragma unroll
    for (int i = 0; i < 4; i++)
        #pragma unroll
        for (int j = 0; j < 4; j++)
            #pragma unroll
            for (int c = 0; c < 4; c++) acc[i][j][c] = 0.0f;

    load_chunk(0, 0);

    for (int ch = 0; ch < NCH; ch++) {
        if (ch + 1 < NCH) {
            load_chunk(ch + 1, (ch + 1) & 1);
            CPA_WAIT(1);
        } else {
            CPA_WAIT(0);
        }
        __syncthreads();

        const uint32_t stg = s_base + (uint32_t)(ch & 1) * STG_SZ;
        const uint32_t s_ahi = stg, s_alo = stg + PL_SZ;
        const uint32_t s_bhi = stg + 2 * PL_SZ, s_blo = stg + 3 * PL_SZ;

        #pragma unroll
        for (int ks = 0; ks < 2; ks++) {
            uint32_t a[4][4], bh[4][2], bl[4][2];

            #pragma unroll
            for (int i = 0; i < 4; i++) {
                int row = wm * 64 + i * 16 + (lid & 15);
                int col = ks * 2 + (lid >> 4);
                LDSM4(a[i][0], a[i][1], a[i][2], a[i][3],
                      s_ahi + sw64(row * 64 + (col << 4)));
            }
            #pragma unroll
            for (int p = 0; p < 2; p++) {
                int row = wn * 32 + p * 16 + ((lid & 7) + ((lid >> 4) << 3));
                int col = ks * 2 + ((lid >> 3) & 1);
                LDSM4(bh[2 * p][0], bh[2 * p][1], bh[2 * p + 1][0], bh[2 * p + 1][1],
                      s_bhi + sw64(row * 64 + (col << 4)));
            }
            // pass 1: A_hi x B_hi
            #pragma unroll
            for (int i = 0; i < 4; i++)
                #pragma unroll
                for (int j = 0; j < 4; j++)
                    MMA16816(acc[i][j], a[i], bh[j][0], bh[j][1]);

            #pragma unroll
            for (int p = 0; p < 2; p++) {
                int row = wn * 32 + p * 16 + ((lid & 7) + ((lid >> 4) << 3));
                int col = ks * 2 + ((lid >> 3) & 1);
                LDSM4(bl[2 * p][0], bl[2 * p][1], bl[2 * p + 1][0], bl[2 * p + 1][1],
                      s_blo + sw64(row * 64 + (col << 4)));
            }
            // pass 2: A_hi x B_lo
            #pragma unroll
            for (int i = 0; i < 4; i++)
                #pragma unroll
                for (int j = 0; j < 4; j++)
                    MMA16816(acc[i][j], a[i], bl[j][0], bl[j][1]);

            #pragma unroll
            for (int i = 0; i < 4; i++) {
                int row = wm * 64 + i * 16 + (lid & 15);
                int col = ks * 2 + (lid >> 4);
                LDSM4(a[i][0], a[i][1], a[i][2], a[i][3],
                      s_alo + sw64(row * 64 + (col << 4)));
            }
            // pass 3: A_lo x B_hi
            #pragma unroll
            for (int i = 0; i < 4; i++)
                #pragma unroll
                for (int j = 0; j < 4; j++)
                    MMA16816(acc[i][j], a[i], bh[j][0], bh[j][1]);
        }
        __syncthreads();   // all warps done with this stage before it is reloaded
    }

    // ---- epilogue: +bias, write fp32 (final) or split bf16 planes ----
    #pragma unroll
    for (int i = 0; i < 4; i++) {
        int r0 = m0 + wm * 64 + i * 16 + (lid >> 2);
        #pragma unroll
        for (int j = 0; j < 4; j++) {
            int gc = n0 + wn * 32 + j * 8 + 2 * (lid & 3);
            float b0 = bias[gc], b1 = bias[gc + 1];
            float v00 = acc[i][j][0] + b0, v01 = acc[i][j][1] + b1;
            float v10 = acc[i][j][2] + b0, v11 = acc[i][j][3] + b1;
            if (FINAL) {
                *(float2*)(Of + (size_t)r0 * HID + gc)        = make_float2(v00, v01);
                *(float2*)(Of + (size_t)(r0 + 8) * HID + gc)  = make_float2(v10, v11);
            } else {
                __nv_bfloat16 h0, l0, h1, l1;
                split2(v00, h0, l0); split2(v01, h1, l1);
                union { __nv_bfloat16 b[2]; uint32_t u; } ph, pl;
                ph.b[0] = h0; ph.b[1] = h1; pl.b[0] = l0; pl.b[1] = l1;
                *(uint32_t*)(Oh + (size_t)r0 * HID + gc) = ph.u;
                *(uint32_t*)(Ol + (size_t)r0 * HID + gc) = pl.u;
                split2(v10, h0, l0); split2(v11, h1, l1);
                ph.b[0] = h0; ph.b[1] = h1; pl.b[0] = l0; pl.b[1] = l1;
                *(uint32_t*)(Oh + (size_t)(r0 + 8) * HID + gc) = ph.u;
                *(uint32_t*)(Ol + (size_t)(r0 + 8) * HID + gc) = pl.u;
            }
        }
    }
}

// ---------------- driver ----------------
extern "C" void kernel_launch(void* const* d_in, const int* in_sizes, int n_in,
                              void* d_out, int out_size) {
    const int*   ids = (const int*)d_in[0];
    const float* emb = (const float*)d_in[1];
    const float* W1  = (const float*)d_in[2];
    const float* b1  = (const float*)d_in[3];
    const float* W2  = (const float*)d_in[4];
    const float* b2  = (const float*)d_in[5];
    float* out = (float*)d_out;

    __nv_bfloat16 *w1h, *w1l, *w2h, *w2l, *eh, *el, *p0h, *p0l, *p1h, *p1l;
    cudaGetSymbolAddress((void**)&w1h, g_w1h);
    cudaGetSymbolAddress((void**)&w1l, g_w1l);
    cudaGetSymbolAddress((void**)&w2h, g_w2h);
    cudaGetSymbolAddress((void**)&w2l, g_w2l);
    cudaGetSymbolAddress((void**)&eh, g_eh);
    cudaGetSymbolAddress((void**)&el, g_el);
    cudaGetSymbolAddress((void**)&p0h, g_p0h);
    cudaGetSymbolAddress((void**)&p0l, g_p0l);
    cudaGetSymbolAddress((void**)&p1h, g_p1h);
    cudaGetSymbolAddress((void**)&p1l, g_p1l);

    cudaFuncSetAttribute(gemm_kernel<1, KP1, 0>, cudaFuncAttributeMaxDynamicSharedMemorySize, SMEM_SZ);
    cudaFuncSetAttribute(gemm_kernel<0, KP2, 0>, cudaFuncAttributeMaxDynamicSharedMemorySize, SMEM_SZ);
    cudaFuncSetAttribute(gemm_kernel<0, KP2, 1>, cudaFuncAttributeMaxDynamicSharedMemorySize, SMEM_SZ);

    prep_w<<<(HID * KP1 + HID * KP2 + 255) / 256, 256>>>(W1, W2);
    {
        size_t n = (size_t)VOCAB * KP1;
        int g = (int)((n + 255) / 256);
        prep_emb<<<g, 256>>>(emb);
    }

    // leaves: [262144, 320] @ W1t -> p0 planes [262144, 256]
    {
        dim3 g(MLEAF / 128, 2);
        gemm_kernel<1, KP1, 0><<<g, TPB, SMEM_SZ>>>(
            ids, eh, el, w1h, w1l, b1, p0h, p0l, nullptr);
    }

    // internal levels: view [rows,256] planes as [rows/2,512]
    int rows = MLEAF;
    __nv_bfloat16 *ch = p0h, *cl = p0l, *oh = p1h, *ol = p1l;
    while (rows > 256) {
        int mout = rows / 2;
        dim3 g(mout / 128, 2);
        if (mout == 256) {
            gemm_kernel<0, KP2, 1><<<g, TPB, SMEM_SZ>>>(
                nullptr, ch, cl, w2h, w2l, b2, nullptr, nullptr, out);
        } else {
            gemm_kernel<0, KP2, 0><<<g, TPB, SMEM_SZ>>>(
                nullptr, ch, cl, w2h, w2l, b2, oh, ol, nullptr);
        }
        __nv_bfloat16* th = ch; __nv_bfloat16* tl = cl;
        ch = oh; cl = ol; oh = th; ol = tl;
        rows = mout;
    }
}

// round 10
// speedup vs baseline: 1.3910x; 1.3531x over previous
#include <cuda_runtime.h>
#include <cuda_bf16.h>
#include <cstdint>

#define DI __device__ __forceinline__

#define HID   256
#define KP1   320        // word dim 300 padded to 320
#define KP2   512
#define MLEAF 262144
#define VOCAB 50257
#define VPAD  50304      // 393 * 128
#define TPB   256

// ---- shared memory: 3-stage pipeline, K-chunk 32 (64B rows) ----
#define SM_IDS   0
#define SM_STAGE 1024
#define STG_SZ   32768
#define PL_SZ    8192
#define SMEM_SZ  (SM_STAGE + 3 * STG_SZ)   // 99328 B -> 2 CTAs/SM

// ---- static device scratch (no allocation allowed) ----
__device__ __align__(256) __nv_bfloat16 g_w1h[HID * KP1];
__device__ __align__(256) __nv_bfloat16 g_w1l[HID * KP1];
__device__ __align__(256) __nv_bfloat16 g_w2h[HID * KP2];
__device__ __align__(256) __nv_bfloat16 g_w2l[HID * KP2];
__device__ __align__(256) __nv_bfloat16 g_eh[(size_t)VPAD * KP1];
__device__ __align__(256) __nv_bfloat16 g_el[(size_t)VPAD * KP1];
__device__ __align__(256) __nv_bfloat16 g_Th[(size_t)VPAD * HID];   // T = E*W1+b1
__device__ __align__(256) __nv_bfloat16 g_Tl[(size_t)VPAD * HID];
__device__ __align__(256) __nv_bfloat16 g_p0h[(size_t)(MLEAF / 2) * HID];
__device__ __align__(256) __nv_bfloat16 g_p0l[(size_t)(MLEAF / 2) * HID];
__device__ __align__(256) __nv_bfloat16 g_p1h[(size_t)(MLEAF / 4) * HID];
__device__ __align__(256) __nv_bfloat16 g_p1l[(size_t)(MLEAF / 4) * HID];

// ---------------- PTX helpers (compute_103-safe ISA only) ----------------
DI uint32_t smem_u32(const void* p) {
    uint32_t a;
    asm("{ .reg .u64 t; cvta.to.shared.u64 t, %1; cvt.u32.u64 %0, t; }" : "=r"(a) : "l"(p));
    return a;
}

#define CPA16(dst, src) \
    asm volatile("cp.async.cg.shared.global [%0], [%1], 16;" :: "r"(dst), "l"(src))
#define CPA_COMMIT() \
    asm volatile("cp.async.commit_group;" ::: "memory")
#define CPA_WAIT(n) \
    asm volatile("cp.async.wait_group %0;" :: "n"(n) : "memory")

#define LDSM4(r0, r1, r2, r3, addr)                                            \
    asm volatile("ldmatrix.sync.aligned.m8n8.x4.shared.b16 {%0,%1,%2,%3}, [%4];" \
                 : "=r"(r0), "=r"(r1), "=r"(r2), "=r"(r3) : "r"(addr))

#define MMA16816(d, a, b0, b1)                                                 \
    asm volatile("mma.sync.aligned.m16n8k16.row.col.f32.bf16.bf16.f32 "        \
                 "{%0,%1,%2,%3}, {%4,%5,%6,%7}, {%8,%9}, {%0,%1,%2,%3};"       \
                 : "+f"((d)[0]), "+f"((d)[1]), "+f"((d)[2]), "+f"((d)[3])      \
                 : "r"((a)[0]), "r"((a)[1]), "r"((a)[2]), "r"((a)[3]),         \
                   "r"(b0), "r"(b1))

DI void split2(float v, __nv_bfloat16& h, __nv_bfloat16& l) {
    h = __float2bfloat16(v);
    l = __float2bfloat16(v - __bfloat162float(h));
}

// 64B-row swizzle: XOR col16 bits[4:5] with row byte bits[7:8]
DI uint32_t sw64(uint32_t off) { return off ^ ((off >> 3) & 0x30); }

// ---------------- prep: split weights (transposed+padded) ----------------
__global__ void prep_w(const float* __restrict__ W1, const float* __restrict__ W2) {
    int i = blockIdx.x * blockDim.x + threadIdx.x;
    if (i < HID * KP1) {
        int n = i / KP1, k = i % KP1;
        float v = (k < 300) ? W1[k * HID + n] : 0.0f;
        __nv_bfloat16 h, l;
        split2(v, h, l);
        g_w1h[i] = h; g_w1l[i] = l;
    } else {
        int j = i - HID * KP1;
        if (j < HID * KP2) {
            int n = j / KP2, k = j % KP2;
            __nv_bfloat16 h, l;
            split2(W2[k * HID + n], h, l);
            g_w2h[j] = h; g_w2l[j] = l;
        }
    }
}

// ---------------- prep: split embedding table (padded rows/cols) ----------------
__global__ void prep_emb(const float* __restrict__ E) {
    size_t i = (size_t)blockIdx.x * blockDim.x + threadIdx.x;
    if (i >= (size_t)VPAD * KP1) return;
    int v = (int)(i / KP1), k = (int)(i % KP1);
    float x = (v < VOCAB && k < 300) ? E[(size_t)v * 300 + k] : 0.0f;
    __nv_bfloat16 h, l;
    split2(x, h, l);
    g_eh[i] = h; g_el[i] = l;
}

// ---------------- GEMM: Out[128,128] = A[128,KPAD] @ Wt[128,KPAD]^T + bias ----
// Split-bf16 3-MMA (hh + hl + lh), 3-stage cp.async pipeline, K-chunk 32.
// MODE 0: A row r = Ah/Al[(m0+r)*KPAD + k]       (direct)
// MODE 1: A row r = concat(T[ids[2r]], T[ids[2r+1]]), KPAD=512, T stride HID
template <int MODE, int KPAD, int FINAL>
__global__ void __launch_bounds__(TPB, 2) gemm_kernel(
    const int* __restrict__ ids,
    const __nv_bfloat16* __restrict__ Ah, const __nv_bfloat16* __restrict__ Al,
    const __nv_bfloat16* __restrict__ Bh, const __nv_bfloat16* __restrict__ Bl,
    const float* __restrict__ bias,
    __nv_bfloat16* __restrict__ Oh, __nv_bfloat16* __restrict__ Ol,
    float* __restrict__ Of)
{
    extern __shared__ char smem[];
    const int tid = threadIdx.x, wid = tid >> 5, lid = tid & 31;
    const int m0 = blockIdx.x * 128, n0 = blockIdx.y * 128;
    const int wm = wid >> 2, wn = wid & 3;              // 2 x 4 warp grid
    int* sids = (int*)smem;

    if (MODE == 1) sids[tid] = ids[m0 * 2 + tid];       // 256 pair-ids
    __syncthreads();

    const uint32_t s_base = smem_u32(smem + SM_STAGE);
    const int NCH = KPAD / 32;

    // loader: all cp.async for chunk ch into stage st
    auto load_chunk = [&](int ch, int st) {
        const uint32_t stg = s_base + (uint32_t)st * STG_SZ;
        #pragma unroll
        for (int v = tid; v < 512; v += TPB) {           // A hi + A lo
            int r = v >> 2, u = v & 3;
            size_t off;
            if (MODE == 1) {
                int id = sids[2 * r + (ch >= NCH / 2)];
                off = (size_t)id * (HID * 2) + (size_t)((ch & (NCH / 2 - 1)) * 64 + u * 16);
            } else {
                off = (size_t)(m0 + r) * (KPAD * 2) + (size_t)(ch * 64 + u * 16);
            }
            uint32_t d = sw64((uint32_t)(r * 64 + u * 16));
            CPA16(stg + d,         (const char*)Ah + off);
            CPA16(stg + PL_SZ + d, (const char*)Al + off);
        }
        #pragma unroll
        for (int v = tid; v < 512; v += TPB) {           // B hi + B lo
            int r = v >> 2, u = v & 3;
            size_t off = (size_t)(n0 + r) * (KPAD * 2) + (size_t)(ch * 64 + u * 16);
            uint32_t d = sw64((uint32_t)(r * 64 + u * 16));
            CPA16(stg + 2 * PL_SZ + d, (const char*)Bh + off);
            CPA16(stg + 3 * PL_SZ + d, (const char*)Bl + off);
        }
        CPA_COMMIT();
    };

    float acc[4][4][4];
    #pragma unroll
    for (int i = 0; i < 4; i++)
        #pragma unroll
        for (int j = 0; j < 4; j++)
            #pragma unroll
            for (int c = 0; c < 4; c++) acc[i][j][c] = 0.0f;

    load_chunk(0, 0);
    load_chunk(1, 1);

    for (int ch = 0; ch < NCH; ch++) {
        if (ch == NCH - 1) { CPA_WAIT(0); } else { CPA_WAIT(1); }
        __syncthreads();   // chunk ch ready; all warps done with stage (ch+2)%3's old data
        if (ch + 2 < NCH) load_chunk(ch + 2, (ch + 2) % 3);

        const uint32_t stg = s_base + (uint32_t)(ch % 3) * STG_SZ;
        const uint32_t s_ahi = stg, s_alo = stg + PL_SZ;
        const uint32_t s_bhi = stg + 2 * PL_SZ, s_blo = stg + 3 * PL_SZ;

        #pragma unroll
        for (int ks = 0; ks < 2; ks++) {
            uint32_t a[4][4], bh[4][2], bl[4][2];

            #pragma unroll
            for (int i = 0; i < 4; i++) {
                int row = wm * 64 + i * 16 + (lid & 15);
                int col = ks * 2 + (lid >> 4);
                LDSM4(a[i][0], a[i][1], a[i][2], a[i][3],
                      s_ahi + sw64(row * 64 + (col << 4)));
            }
            #pragma unroll
            for (int p = 0; p < 2; p++) {
                int row = wn * 32 + p * 16 + ((lid & 7) + ((lid >> 4) << 3));
                int col = ks * 2 + ((lid >> 3) & 1);
                LDSM4(bh[2 * p][0], bh[2 * p][1], bh[2 * p + 1][0], bh[2 * p + 1][1],
                      s_bhi + sw64(row * 64 + (col << 4)));
            }
            // pass 1: A_hi x B_hi
            #pragma unroll
            for (int i = 0; i < 4; i++)
                #pragma unroll
                for (int j = 0; j < 4; j++)
                    MMA16816(acc[i][j], a[i], bh[j][0], bh[j][1]);

            #pragma unroll
            for (int p = 0; p < 2; p++) {
                int row = wn * 32 + p * 16 + ((lid & 7) + ((lid >> 4) << 3));
                int col = ks * 2 + ((lid >> 3) & 1);
                LDSM4(bl[2 * p][0], bl[2 * p][1], bl[2 * p + 1][0], bl[2 * p + 1][1],
                      s_blo + sw64(row * 64 + (col << 4)));
            }
            // pass 2: A_hi x B_lo
            #pragma unroll
            for (int i = 0; i < 4; i++)
                #pragma unroll
                for (int j = 0; j < 4; j++)
                    MMA16816(acc[i][j], a[i], bl[j][0], bl[j][1]);

            #pragma unroll
            for (int i = 0; i < 4; i++) {
                int row = wm * 64 + i * 16 + (lid & 15);
                int col = ks * 2 + (lid >> 4);
                LDSM4(a[i][0], a[i][1], a[i][2], a[i][3],
                      s_alo + sw64(row * 64 + (col << 4)));
            }
            // pass 3: A_lo x B_hi
            #pragma unroll
            for (int i = 0; i < 4; i++)
                #pragma unroll
                for (int j = 0; j < 4; j++)
                    MMA16816(acc[i][j], a[i], bh[j][0], bh[j][1]);
        }
    }

    // ---- epilogue: +bias, write fp32 (final) or split bf16 planes ----
    #pragma unroll
    for (int i = 0; i < 4; i++) {
        int r0 = m0 + wm * 64 + i * 16 + (lid >> 2);
        #pragma unroll
        for (int j = 0; j < 4; j++) {
            int gc = n0 + wn * 32 + j * 8 + 2 * (lid & 3);
            float b0 = bias[gc], b1 = bias[gc + 1];
            float v00 = acc[i][j][0] + b0, v01 = acc[i][j][1] + b1;
            float v10 = acc[i][j][2] + b0, v11 = acc[i][j][3] + b1;
            if (FINAL) {
                *(float2*)(Of + (size_t)r0 * HID + gc)        = make_float2(v00, v01);
                *(float2*)(Of + (size_t)(r0 + 8) * HID + gc)  = make_float2(v10, v11);
            } else {
                __nv_bfloat16 h0, l0, h1, l1;
                split2(v00, h0, l0); split2(v01, h1, l1);
                union { __nv_bfloat16 b[2]; uint32_t u; } ph, pl;
                ph.b[0] = h0; ph.b[1] = h1; pl.b[0] = l0; pl.b[1] = l1;
                *(uint32_t*)(Oh + (size_t)r0 * HID + gc) = ph.u;
                *(uint32_t*)(Ol + (size_t)r0 * HID + gc) = pl.u;
                split2(v10, h0, l0); split2(v11, h1, l1);
                ph.b[0] = h0; ph.b[1] = h1; pl.b[0] = l0; pl.b[1] = l1;
                *(uint32_t*)(Oh + (size_t)(r0 + 8) * HID + gc) = ph.u;
                *(uint32_t*)(Ol + (size_t)(r0 + 8) * HID + gc) = pl.u;
            }
        }
    }
}

// ---------------- driver ----------------
extern "C" void kernel_launch(void* const* d_in, const int* in_sizes, int n_in,
                              void* d_out, int out_size) {
    const int*   ids = (const int*)d_in[0];
    const float* emb = (const float*)d_in[1];
    const float* W1  = (const float*)d_in[2];
    const float* b1  = (const float*)d_in[3];
    const float* W2  = (const float*)d_in[4];
    const float* b2  = (const float*)d_in[5];
    float* out = (float*)d_out;

    __nv_bfloat16 *w1h, *w1l, *w2h, *w2l, *eh, *el, *th, *tl, *p0h, *p0l, *p1h, *p1l;
    cudaGetSymbolAddress((void**)&w1h, g_w1h);
    cudaGetSymbolAddress((void**)&w1l, g_w1l);
    cudaGetSymbolAddress((void**)&w2h, g_w2h);
    cudaGetSymbolAddress((void**)&w2l, g_w2l);
    cudaGetSymbolAddress((void**)&eh, g_eh);
    cudaGetSymbolAddress((void**)&el, g_el);
    cudaGetSymbolAddress((void**)&th, g_Th);
    cudaGetSymbolAddress((void**)&tl, g_Tl);
    cudaGetSymbolAddress((void**)&p0h, g_p0h);
    cudaGetSymbolAddress((void**)&p0l, g_p0l);
    cudaGetSymbolAddress((void**)&p1h, g_p1h);
    cudaGetSymbolAddress((void**)&p1l, g_p1l);

    cudaFuncSetAttribute(gemm_kernel<0, KP1, 0>, cudaFuncAttributeMaxDynamicSharedMemorySize, SMEM_SZ);
    cudaFuncSetAttribute(gemm_kernel<1, KP2, 0>, cudaFuncAttributeMaxDynamicSharedMemorySize, SMEM_SZ);
    cudaFuncSetAttribute(gemm_kernel<0, KP2, 0>, cudaFuncAttributeMaxDynamicSharedMemorySize, SMEM_SZ);
    cudaFuncSetAttribute(gemm_kernel<0, KP2, 1>, cudaFuncAttributeMaxDynamicSharedMemorySize, SMEM_SZ);

    prep_w<<<(HID * KP1 + HID * KP2 + 255) / 256, 256>>>(W1, W2);
    {
        size_t n = (size_t)VPAD * KP1;
        int g = (int)((n + 255) / 256);
        prep_emb<<<g, 256>>>(emb);
    }

    // T = E @ W1t + b1 over the (padded) vocab: [50304, 320] -> [50304, 256]
    {
        dim3 g(VPAD / 128, 2);
        gemm_kernel<0, KP1, 0><<<g, TPB, SMEM_SZ>>>(
            nullptr, eh, el, w1h, w1l, b1, th, tl, nullptr);
    }

    // level 1: gather pairs of T rows as A = [131072, 512] -> p0 [131072, 256]
    {
        dim3 g((MLEAF / 2) / 128, 2);
        gemm_kernel<1, KP2, 0><<<g, TPB, SMEM_SZ>>>(
            ids, th, tl, w2h, w2l, b2, p0h, p0l, nullptr);
    }

    // levels 2+: view [rows,256] planes as [rows/2,512]
    int rows = MLEAF / 2;
    __nv_bfloat16 *ch = p0h, *cl = p0l, *oh = p1h, *ol = p1l;
    while (rows > 256) {
        int mout = rows / 2;
        dim3 g(mout / 128, 2);
        if (mout == 256) {
            gemm_kernel<0, KP2, 1><<<g, TPB, SMEM_SZ>>>(
                nullptr, ch, cl, w2h, w2l, b2, nullptr, nullptr, out);
        } else {
            gemm_kernel<0, KP2, 0><<<g, TPB, SMEM_SZ>>>(
                nullptr, ch, cl, w2h, w2l, b2, oh, ol, nullptr);
        }
        __nv_bfloat16* t0 = ch; __nv_bfloat16* t1 = cl;
        ch = oh; cl = ol; oh = t0; ol = t1;
        rows = mout;
    }
}